// round 6
// baseline (speedup 1.0000x reference)
#include <cuda_runtime.h>
#include <cuda_fp16.h>
#include <math.h>
#include <stdint.h>

#define NVIEW 5
#define NBINS 128000
#define BATCH 2
#define HF 128
#define WF 128
#define HWF (HF*WF)
#define HI 512
#define WI 512
#define HWI (HI*WI)
#define CF 32
#define HID 256
#define MTOT (BATCH*NBINS)     // 256000
#define TILE_M 128
#define NTILES (MTOT/TILE_M)   // 2000
#define PGRID 148

// GEMM K geometry: permuted input dims, KPAD=80 (5 k16-steps), row = 44 words
#define KPAD 80
#define NK16 5
#define WROW 44                 // uint32 words per row (40 used + pad)
#define B_WORDS (2*HID*WROW)    // 22528
#define A_WORDS (2*TILE_M*WROW) // 11264

// ---------------- scratch (device globals: allocation-free) ----------------
__device__ float4 g_imgs_t[NVIEW*BATCH*HWI];
__device__ float4 g_feats_t[NVIEW*BATCH*HWF*(CF/4)];
__device__ uint4  g_B[B_WORDS/4];   // W1^T fp16 hi/lo planes, fragment word order

// word index inside a row for even k (pairs grouped per k16 step: klow|khigh)
__device__ __host__ constexpr int word_of(int k) {
    return 8*(k >> 4) + (((k & 15) < 8) ? (k & 15) : ((k & 15) - 7));
}

// permuted col -> original input dim (orig: [pts3, mean img3+feat32, var img3+feat32])
__device__ __forceinline__ int orig_of(int c) {
    if (c < 22) return c;                 // pts, img mean, feat mean 0-15
    if (c < 25) return 38 + (c - 22);     // img var
    if (c < 41) return 41 + (c - 25);     // feat var 0-15
    if (c == 41) return -1;               // pad
    if (c < 58) return 22 + (c - 42);     // feat mean 16-31
    if (c < 74) return 57 + (c - 58);     // feat var 16-31
    return -1;                            // pad
}

__device__ __forceinline__ uint32_t pack_h2(__half a, __half b) {
    return (uint32_t)__half_as_ushort(a) | ((uint32_t)__half_as_ushort(b) << 16);
}

#define MMA16816(d, a0, a1, a2, a3, b0, b1) \
    asm volatile("mma.sync.aligned.m16n8k16.row.col.f32.f16.f16.f32 " \
        "{%0,%1,%2,%3}, {%4,%5,%6,%7}, {%8,%9}, {%0,%1,%2,%3};" \
        : "+f"((d)[0]), "+f"((d)[1]), "+f"((d)[2]), "+f"((d)[3]) \
        : "r"(a0), "r"(a1), "r"(a2), "r"(a3), "r"(b0), "r"(b1))

// ---------------- kernel 0: prep W1 -> fp16 hi/lo fragment-ordered planes ----------------
__global__ void prep_B(const float* __restrict__ W1) {
    int i = blockIdx.x * 256 + threadIdx.x;    // over 256 n * 40 pairs
    if (i >= HID * 40) return;
    int n = i / 40;
    int k = (i - n * 40) * 2;
    int o0 = orig_of(k), o1 = orig_of(k + 1);
    float v0 = (o0 >= 0) ? W1[o0 * HID + n] : 0.f;
    float v1 = (o1 >= 0) ? W1[o1 * HID + n] : 0.f;
    __half h0 = __float2half_rn(v0), h1 = __float2half_rn(v1);
    __half l0 = __float2half_rn(v0 - __half2float(h0));
    __half l1 = __float2half_rn(v1 - __half2float(h1));
    int w = word_of(k);
    uint32_t* gb = (uint32_t*)g_B;
    gb[0 * HID * WROW + n * WROW + w] = pack_h2(h0, h1);
    gb[1 * HID * WROW + n * WROW + w] = pack_h2(l0, l1);
}

// ---------------- layout transposes ----------------
__global__ void transpose_imgs(const float* __restrict__ im) {
    int idx = blockIdx.x * blockDim.x + threadIdx.x;
    if (idx >= NVIEW*BATCH*HWI) return;
    int vb = idx >> 18;
    int p  = idx & (HWI - 1);
    const float* base = im + (size_t)vb * 3 * HWI + p;
    g_imgs_t[idx] = make_float4(base[0], base[HWI], base[2*HWI], 0.f);
}
__global__ void transpose_feats(const float* __restrict__ f) {
    __shared__ float tile[32][33];
    int vb = blockIdx.y;
    int p0 = blockIdx.x * 32;
    int tx = threadIdx.x, ty = threadIdx.y;
    tile[ty][tx] = f[((size_t)vb*CF + ty) * HWF + p0 + tx];
    __syncthreads();
    ((float*)g_feats_t)[((size_t)vb*HWF + p0 + ty) * CF + tx] = tile[tx][ty];
}

// ---------------- persistent fused kernel: gather -> smem A -> HMMA -> epilogue ----------
// smem words: Bhi[256*44] Blo[256*44] Ahi[128*44] Alo[128*44] bw[256*2] zbuf[128*2]
#define SMEM_WORDS (B_WORDS + A_WORDS + 512 + 256)
#define SMEM_BYTES (SMEM_WORDS * 4)

__global__ __launch_bounds__(256, 1)
void fused_kernel(const float* __restrict__ grid_, const float* __restrict__ pts,
                  const float* __restrict__ b1, const float* __restrict__ W2,
                  const float* __restrict__ b2, float* __restrict__ out) {
    extern __shared__ uint32_t sm[];
    uint32_t* Bs0 = sm;
    uint32_t* Bs1 = sm + HID*WROW;
    uint32_t* As0 = sm + B_WORDS;
    uint32_t* As1 = As0 + TILE_M*WROW;
    float2*  bwS  = (float2*)(sm + B_WORDS + A_WORDS);
    float*   zbuf = (float*)(bwS + HID);

    int tid = threadIdx.x;
    int lane = tid & 31;
    int wid  = tid >> 5;

    // ---- one-time: B planes to smem + bias/W2 pairs ----
    {
        const uint4* src = g_B;
        uint4* dst = (uint4*)sm;
#pragma unroll 4
        for (int i = tid; i < B_WORDS/4; i += 256) dst[i] = src[i];
        if (tid < HID) bwS[tid] = make_float2(b1[tid], W2[tid]);
    }
    __syncthreads();

    float b2v = b2[0];
    int half = tid >> 7;           // warps 0-3: half0, 4-7: half1
    int r    = tid & 127;          // local point / output row

    // mma warp tiling: 4 m-warps x 2 n-warps
    int mw = wid & 3, nw = wid >> 2;
    int mbase = mw * 32;
    int nbase = nw * 128;
    int g  = lane >> 2;
    int t4 = lane & 3;

    for (int t = blockIdx.x; t < NTILES; t += gridDim.x) {
        // ================= Phase A: gather -> smem A (fp16 hi/lo fragments) =============
        {
            int m = t * TILE_M + r;
            int b = m / NBINS;
            int n = m - b * NBINS;

            float s[19], ss[19];
#pragma unroll
            for (int c = 0; c < 19; c++) { s[c] = 0.f; ss[c] = 0.f; }

#pragma unroll
            for (int v = 0; v < NVIEW; v++) {
                float gx = grid_[((size_t)v*NBINS + n)*2 + 0];
                float gy = grid_[((size_t)v*NBINS + n)*2 + 1];
                // features: 16 channels per half
                {
                    float fx = (gx + 1.f) * 0.5f * (float)(WF - 1);
                    float fy = (gy + 1.f) * 0.5f * (float)(HF - 1);
                    float x0f = floorf(fx), y0f = floorf(fy);
                    float wx1 = fx - x0f, wy1 = fy - y0f;
                    float wx0 = 1.f - wx1, wy0 = 1.f - wy1;
                    int x0 = max(0, min((int)x0f, WF-1));
                    int y0 = max(0, min((int)y0f, HF-1));
                    int x1 = min(x0 + 1, WF-1);
                    int y1 = min(y0 + 1, HF-1);
                    float w00 = wx0*wy0, w01 = wx1*wy0, w10 = wx0*wy1, w11 = wx1*wy1;
                    int base = (v*BATCH + b) * HWF;
                    int c4base = half * 4;
                    int b00 = (base + y0*WF + x0) * (CF/4) + c4base;
                    int b01 = (base + y0*WF + x1) * (CF/4) + c4base;
                    int b10 = (base + y1*WF + x0) * (CF/4) + c4base;
                    int b11 = (base + y1*WF + x1) * (CF/4) + c4base;
#pragma unroll
                    for (int c4 = 0; c4 < 4; c4++) {
                        float4 q00 = g_feats_t[b00 + c4];
                        float4 q01 = g_feats_t[b01 + c4];
                        float4 q10 = g_feats_t[b10 + c4];
                        float4 q11 = g_feats_t[b11 + c4];
                        int c = c4*4;
                        float tt;
                        tt = w00*q00.x + w01*q01.x + w10*q10.x + w11*q11.x; s[c+0]+=tt; ss[c+0]+=tt*tt;
                        tt = w00*q00.y + w01*q01.y + w10*q10.y + w11*q11.y; s[c+1]+=tt; ss[c+1]+=tt*tt;
                        tt = w00*q00.z + w01*q01.z + w10*q10.z + w11*q11.z; s[c+2]+=tt; ss[c+2]+=tt*tt;
                        tt = w00*q00.w + w01*q01.w + w10*q10.w + w11*q11.w; s[c+3]+=tt; ss[c+3]+=tt*tt;
                    }
                }
                if (half == 0) {
                    float fx = (gx + 1.f) * 0.5f * (float)(WI - 1);
                    float fy = (gy + 1.f) * 0.5f * (float)(HI - 1);
                    float x0f = floorf(fx), y0f = floorf(fy);
                    float wx1 = fx - x0f, wy1 = fy - y0f;
                    float wx0 = 1.f - wx1, wy0 = 1.f - wy1;
                    int x0 = max(0, min((int)x0f, WI-1));
                    int y0 = max(0, min((int)y0f, HI-1));
                    int x1 = min(x0 + 1, WI-1);
                    int y1 = min(y0 + 1, HI-1);
                    float w00 = wx0*wy0, w01 = wx1*wy0, w10 = wx0*wy1, w11 = wx1*wy1;
                    int base = (v*BATCH + b) * HWI;
                    float4 p00 = g_imgs_t[base + y0*WI + x0];
                    float4 p01 = g_imgs_t[base + y0*WI + x1];
                    float4 p10 = g_imgs_t[base + y1*WI + x0];
                    float4 p11 = g_imgs_t[base + y1*WI + x1];
                    float r0 = w00*p00.x + w01*p01.x + w10*p10.x + w11*p11.x;
                    float r1 = w00*p00.y + w01*p01.y + w10*p10.y + w11*p11.y;
                    float r2 = w00*p00.z + w01*p01.z + w10*p10.z + w11*p11.z;
                    s[16] += r0; ss[16] += r0*r0;
                    s[17] += r1; ss[17] += r1*r1;
                    s[18] += r2; ss[18] += r2*r2;
                }
            }

            // values for this half's permuted columns, then hi/lo pack into smem
            if (half == 0) {
                float vv[42];
                vv[0] = pts[n*3 + 0]; vv[1] = pts[n*3 + 1]; vv[2] = pts[n*3 + 2];
#pragma unroll
                for (int c = 0; c < 3; c++) {     // img: mean cols 3-5, var cols 22-24
                    float mean = s[16+c] * 0.2f;
                    float var  = fmaxf(ss[16+c] * 0.2f - mean*mean, 0.f);
                    vv[3 + c]  = mean;
                    vv[22 + c] = expf(-var);
                }
#pragma unroll
                for (int f = 0; f < 16; f++) {    // feat 0-15: mean 6+f, var 25+f
                    float mean = s[f] * 0.2f;
                    float var  = fmaxf(ss[f] * 0.2f - mean*mean, 0.f);
                    vv[6 + f]  = mean;
                    vv[25 + f] = expf(-var);
                }
                vv[41] = 0.f;
#pragma unroll
                for (int k = 0; k < 42; k += 2) {
                    int w = word_of(k);
                    __half h0 = __float2half_rn(vv[k]),   h1 = __float2half_rn(vv[k+1]);
                    __half l0 = __float2half_rn(vv[k]   - __half2float(h0));
                    __half l1 = __float2half_rn(vv[k+1] - __half2float(h1));
                    As0[r*WROW + w] = pack_h2(h0, h1);
                    As1[r*WROW + w] = pack_h2(l0, l1);
                }
            } else {
                float vv[38];                      // cols 42..79
#pragma unroll
                for (int f = 0; f < 16; f++) {    // feat 16-31: mean 42+f, var 58+f
                    float mean = s[f] * 0.2f;
                    float var  = fmaxf(ss[f] * 0.2f - mean*mean, 0.f);
                    vv[f]      = mean;
                    vv[16 + f] = expf(-var);
                }
#pragma unroll
                for (int c = 32; c < 38; c++) vv[c] = 0.f;   // cols 74..79 pad
#pragma unroll
                for (int kk = 0; kk < 38; kk += 2) {
                    int k = 42 + kk;
                    int w = word_of(k);
                    __half h0 = __float2half_rn(vv[kk]),   h1 = __float2half_rn(vv[kk+1]);
                    __half l0 = __float2half_rn(vv[kk]   - __half2float(h0));
                    __half l1 = __float2half_rn(vv[kk+1] - __half2float(h1));
                    As0[r*WROW + w] = pack_h2(h0, h1);
                    As1[r*WROW + w] = pack_h2(l0, l1);
                }
            }
        }
        __syncthreads();

        // ================= Phase B: 3-pass fp16-split HMMA =================
        float acc[2][16][4];
#pragma unroll
        for (int mt = 0; mt < 2; mt++)
#pragma unroll
            for (int j = 0; j < 16; j++)
#pragma unroll
                for (int c = 0; c < 4; c++) acc[mt][j][c] = 0.f;

#pragma unroll
        for (int s5 = 0; s5 < NK16; s5++) {
            uint2 aH[2][2], aL[2][2];    // [mt][rowhalf] = (klow_pair, khigh_pair)
#pragma unroll
            for (int mt = 0; mt < 2; mt++) {
                int row = mbase + mt*16 + g;
                int o = row*WROW + s5*8 + t4*2;
                aH[mt][0] = *(const uint2*)(As0 + o);
                aH[mt][1] = *(const uint2*)(As0 + o + 8*WROW);
                aL[mt][0] = *(const uint2*)(As1 + o);
                aL[mt][1] = *(const uint2*)(As1 + o + 8*WROW);
            }
#pragma unroll
            for (int j = 0; j < 16; j++) {
                int n0 = nbase + j*8;
                int ob = (n0 + g)*WROW + s5*8 + t4*2;
                uint2 bh = *(const uint2*)(Bs0 + ob);
                uint2 bl = *(const uint2*)(Bs1 + ob);
#pragma unroll
                for (int mt = 0; mt < 2; mt++) {
                    MMA16816(acc[mt][j], aH[mt][0].x, aH[mt][1].x, aH[mt][0].y, aH[mt][1].y, bh.x, bh.y);
                    MMA16816(acc[mt][j], aL[mt][0].x, aL[mt][1].x, aL[mt][0].y, aL[mt][1].y, bh.x, bh.y);
                    MMA16816(acc[mt][j], aH[mt][0].x, aH[mt][1].x, aH[mt][0].y, aH[mt][1].y, bl.x, bl.y);
                }
            }
        }

        // ================= Phase C: epilogue (relu + W2-dot + reduce) =================
        {
            float zp[4] = {0.f, 0.f, 0.f, 0.f};   // [mt*2 + rowhalf]
#pragma unroll
            for (int j = 0; j < 16; j++) {
                int c0 = nbase + j*8 + t4*2;
                float2 bw0 = bwS[c0];
                float2 bw1 = bwS[c0 + 1];
#pragma unroll
                for (int mt = 0; mt < 2; mt++) {
                    zp[mt*2 + 0] += fmaxf(acc[mt][j][0] + bw0.x, 0.f) * bw0.y
                                  + fmaxf(acc[mt][j][1] + bw1.x, 0.f) * bw1.y;
                    zp[mt*2 + 1] += fmaxf(acc[mt][j][2] + bw0.x, 0.f) * bw0.y
                                  + fmaxf(acc[mt][j][3] + bw1.x, 0.f) * bw1.y;
                }
            }
#pragma unroll
            for (int i = 0; i < 4; i++) {
                zp[i] += __shfl_xor_sync(0xffffffffu, zp[i], 1);
                zp[i] += __shfl_xor_sync(0xffffffffu, zp[i], 2);
            }
            if (t4 == 0) {
#pragma unroll
                for (int mt = 0; mt < 2; mt++)
#pragma unroll
                    for (int rh = 0; rh < 2; rh++) {
                        int row = mbase + mt*16 + rh*8 + g;
                        zbuf[row*2 + nw] = zp[mt*2 + rh];
                    }
            }
        }
        __syncthreads();

        if (tid < 128) {
            float zz = zbuf[tid*2] + zbuf[tid*2 + 1] + b2v;
            // 1 - exp(-softplus(zz)) == sigmoid(zz)
            out[t * TILE_M + tid] = 1.f / (1.f + expf(-zz));
        }
        // next tile's gather writes As; zbuf rewritten only after the next
        // post-gather __syncthreads -> no hazard.
    }
}

// ---------------- launch ----------------
extern "C" void kernel_launch(void* const* d_in, const int* in_sizes, int n_in,
                              void* d_out, int out_size) {
    const float* imgs  = (const float*)d_in[0];
    const float* feats = (const float*)d_in[1];
    const float* grid  = (const float*)d_in[2];
    const float* pts   = (const float*)d_in[3];
    const float* W1    = (const float*)d_in[4];
    const float* b1    = (const float*)d_in[5];
    const float* W2    = (const float*)d_in[6];
    const float* b2    = (const float*)d_in[7];
    float* out = (float*)d_out;

    cudaFuncSetAttribute(fused_kernel, cudaFuncAttributeMaxDynamicSharedMemorySize, SMEM_BYTES);

    prep_B<<<(HID*40 + 255)/256, 256>>>(W1);
    transpose_imgs<<<(NVIEW*BATCH*HWI + 255)/256, 256>>>(imgs);
    transpose_feats<<<dim3(HWF/32, NVIEW*BATCH), dim3(32, 32)>>>(feats);
    fused_kernel<<<PGRID, 256, SMEM_BYTES>>>(grid, pts, b1, W2, b2, out);
}

// round 8
// speedup vs baseline: 1.2830x; 1.2830x over previous
#include <cuda_runtime.h>
#include <cuda_fp16.h>
#include <math.h>
#include <stdint.h>

#define NVIEW 5
#define NBINS 128000
#define BATCH 2
#define HF 128
#define WF 128
#define HWF (HF*WF)
#define HI 512
#define WI 512
#define HWI (HI*WI)
#define CF 32
#define HID 256
#define INDIM 73
#define MTOT (BATCH*NBINS)     // 256000

// K geometry: KPAD=80 = 5 k16-steps. Permuted columns in 16-aligned blocks:
// block0 (cols 0-15):  pts0-2, imgmean0-2, imgvar0-2, pad x7
// block 1+cg (16+16cg): feat mean ch[8cg..8cg+8) at i<8, feat var same chans at i>=8
#define NK16 5
#define AROW 40                 // words per A row in global (40 = 80 cols / 2)
#define WROW 44                 // words per B row in smem (padded for banks)
#define B_WORDS (2*HID*WROW)    // hi+lo planes

// ---------------- scratch (device globals: allocation-free) ----------------
__device__ float4   g_imgs_t[NVIEW*BATCH*HWI];           // [vb][pix] rgba
__device__ float4   g_feats_t[NVIEW*BATCH*HWF*(CF/4)];   // [vb][pix][32ch]
__device__ uint32_t g_B[B_WORDS];                        // W1^T fp16 hi/lo planes
__device__ uint32_t g_A[2*MTOT*AROW];                    // A fp16 hi/lo planes (82MB)

// word index inside a row for even k (m16n8k16 fragment grouping)
__device__ __host__ constexpr int word_of(int k) {
    return 8*(k >> 4) + (((k & 15) < 8) ? (k & 15) : ((k & 15) - 7));
}

// permuted col -> original input dim (orig: [pts3, mean img3+feat32, var img3+feat32])
__device__ __forceinline__ int orig_of(int c) {
    int blk = c >> 4, i = c & 15;
    if (blk == 0) {
        if (i < 3) return i;              // pts
        if (i < 6) return 3 + (i - 3);    // img mean
        if (i < 9) return 38 + (i - 6);   // img var
        return -1;                        // pad
    }
    int cg = blk - 1;
    if (i < 8) return 6 + 8*cg + i;       // feat mean
    return 41 + 8*cg + (i - 8);           // feat var
}

__device__ __forceinline__ uint32_t pack_h2(float a, float b) {
    __half ha = __float2half_rn(a), hb = __float2half_rn(b);
    return (uint32_t)__half_as_ushort(ha) | ((uint32_t)__half_as_ushort(hb) << 16);
}
__device__ __forceinline__ uint32_t pack_lo2(float a, float b) {
    __half ha = __float2half_rn(a), hb = __float2half_rn(b);
    float la = a - __half2float(ha), lb = b - __half2float(hb);
    return pack_h2(la, lb);
}

#define MMA16816(d, a0, a1, a2, a3, b0, b1) \
    asm volatile("mma.sync.aligned.m16n8k16.row.col.f32.f16.f16.f32 " \
        "{%0,%1,%2,%3}, {%4,%5,%6,%7}, {%8,%9}, {%0,%1,%2,%3};" \
        : "+f"((d)[0]), "+f"((d)[1]), "+f"((d)[2]), "+f"((d)[3]) \
        : "r"(a0), "r"(a1), "r"(a2), "r"(a3), "r"(b0), "r"(b1))

// ---------------- kernel 0: prep W1 -> fp16 hi/lo fragment-ordered planes ----------------
__global__ void prep_B(const float* __restrict__ W1) {
    int i = blockIdx.x * 256 + threadIdx.x;    // over 256 n * 40 pairs
    if (i >= HID * 40) return;
    int n = i / 40;
    int k = (i - n * 40) * 2;
    int o0 = orig_of(k), o1 = orig_of(k + 1);
    float v0 = (o0 >= 0) ? W1[o0 * HID + n] : 0.f;
    float v1 = (o1 >= 0) ? W1[o1 * HID + n] : 0.f;
    int w = word_of(k);
    g_B[0 * HID * WROW + n * WROW + w] = pack_h2(v0, v1);
    g_B[1 * HID * WROW + n * WROW + w] = pack_lo2(v0, v1);
}

// ---------------- layout transposes ----------------
__global__ void transpose_imgs(const float* __restrict__ im) {
    int idx = blockIdx.x * blockDim.x + threadIdx.x;
    if (idx >= NVIEW*BATCH*HWI) return;
    int vb = idx >> 18;
    int p  = idx & (HWI - 1);
    const float* base = im + (size_t)vb * 3 * HWI + p;
    g_imgs_t[idx] = make_float4(base[0], base[HWI], base[2*HWI], 0.f);
}
__global__ void transpose_feats(const float* __restrict__ f) {
    __shared__ float tile[32][33];
    int vb = blockIdx.y;
    int p0 = blockIdx.x * 32;
    int tx = threadIdx.x, ty = threadIdx.y;
    tile[ty][tx] = f[((size_t)vb*CF + ty) * HWF + p0 + tx];
    __syncthreads();
    ((float*)g_feats_t)[((size_t)vb*HWF + p0 + ty) * CF + tx] = tile[tx][ty];
}

// ---------------- gather kernel: coalesced bilinear, 2 pts/warp, lane=channel-pair ----
// Writes fp16 hi/lo A-fragments to g_A. 256 threads = 16 points/block.
__global__ __launch_bounds__(256)
void gather_kernel(const float* __restrict__ grid_, const float* __restrict__ pts) {
    int tid = blockIdx.x * 256 + threadIdx.x;
    int l   = threadIdx.x & 31;
    int q   = l & 15;                   // channel-pair: feat chans (2q, 2q+1)
    int m   = (tid >> 5) * 2 + (l >> 4);
    int b   = m / NBINS;
    int n   = m - b * NBINS;

    float2 s2  = make_float2(0.f, 0.f), ss2 = make_float2(0.f, 0.f);
    float  si = 0.f, ssi = 0.f;         // img channel q (valid for q<3)

#pragma unroll
    for (int v = 0; v < NVIEW; v++) {
        float2 g = *(const float2*)(grid_ + ((size_t)v*NBINS + n)*2);

        // ---- feats (128x128) ----
        {
            float fx = (g.x + 1.f) * 0.5f * (float)(WF - 1);
            float fy = (g.y + 1.f) * 0.5f * (float)(HF - 1);
            float x0f = floorf(fx), y0f = floorf(fy);
            float wx1 = fx - x0f, wy1 = fy - y0f;
            float wx0 = 1.f - wx1, wy0 = 1.f - wy1;
            int x0 = max(0, min((int)x0f, WF-1));
            int y0 = max(0, min((int)y0f, HF-1));
            int x1 = min(x0 + 1, WF-1);
            int y1 = min(y0 + 1, HF-1);
            float w00 = wx0*wy0, w01 = wx1*wy0, w10 = wx0*wy1, w11 = wx1*wy1;
            int base = (v*BATCH + b) * HWF;
            const char* fb = (const char*)g_feats_t;
            float2 p00 = *(const float2*)(fb + ((size_t)(base + y0*WF + x0))*128 + q*8);
            float2 p01 = *(const float2*)(fb + ((size_t)(base + y0*WF + x1))*128 + q*8);
            float2 p10 = *(const float2*)(fb + ((size_t)(base + y1*WF + x0))*128 + q*8);
            float2 p11 = *(const float2*)(fb + ((size_t)(base + y1*WF + x1))*128 + q*8);
            float vx = w00*p00.x + w01*p01.x + w10*p10.x + w11*p11.x;
            float vy = w00*p00.y + w01*p01.y + w10*p10.y + w11*p11.y;
            s2.x += vx; ss2.x += vx*vx;
            s2.y += vy; ss2.y += vy*vy;
        }
        // ---- imgs (512x512), channel q for q<3 ----
        {
            float fx = (g.x + 1.f) * 0.5f * (float)(WI - 1);
            float fy = (g.y + 1.f) * 0.5f * (float)(HI - 1);
            float x0f = floorf(fx), y0f = floorf(fy);
            float wx1 = fx - x0f, wy1 = fy - y0f;
            float wx0 = 1.f - wx1, wy0 = 1.f - wy1;
            int x0 = max(0, min((int)x0f, WI-1));
            int y0 = max(0, min((int)y0f, HI-1));
            int x1 = min(x0 + 1, WI-1);
            int y1 = min(y0 + 1, HI-1);
            float w00 = wx0*wy0, w01 = wx1*wy0, w10 = wx0*wy1, w11 = wx1*wy1;
            int base = (v*BATCH + b) * HWI;
            const char* ib = (const char*)g_imgs_t;
            float vv = 0.f;
            if (q < 3) {
                float p00 = *(const float*)(ib + ((size_t)(base + y0*WI + x0))*16 + q*4);
                float p01 = *(const float*)(ib + ((size_t)(base + y0*WI + x1))*16 + q*4);
                float p10 = *(const float*)(ib + ((size_t)(base + y1*WI + x0))*16 + q*4);
                float p11 = *(const float*)(ib + ((size_t)(base + y1*WI + x1))*16 + q*4);
                vv = w00*p00 + w01*p01 + w10*p10 + w11*p11;
            }
            si += vv; ssi += vv*vv;
        }
    }

    // ---- finalize ----
    float mean0 = s2.x * 0.2f, mean1 = s2.y * 0.2f;
    float ev0 = expf(-fmaxf(ss2.x * 0.2f - mean0*mean0, 0.f));
    float ev1 = expf(-fmaxf(ss2.y * 0.2f - mean1*mean1, 0.f));
    float im  = si * 0.2f;
    float iv  = expf(-fmaxf(ssi * 0.2f - im*im, 0.f));

    uint32_t* rowH = g_A + (size_t)m * AROW;
    uint32_t* rowL = g_A + (size_t)(MTOT + m) * AROW;

    // feat words: blocks 1-4; cg = q>>2, idx = 2*(q&3); mean word then var word adjacent
    {
        int wslot = 8*(1 + (q >> 2)) + 2*(q & 3);
        uint2 hi = make_uint2(pack_h2(mean0, mean1), pack_h2(ev0, ev1));
        uint2 lo = make_uint2(pack_lo2(mean0, mean1), pack_lo2(ev0, ev1));
        *(uint2*)(rowH + wslot) = hi;
        *(uint2*)(rowL + wslot) = lo;
    }

    // gather img chans 1,2 stats into q==0 lane (lanes 0..2 of each 16-lane group hold them)
    unsigned grp = (unsigned)(l & 16);
    float im1 = __shfl_sync(0xffffffffu, im, grp | 1);
    float im2 = __shfl_sync(0xffffffffu, im, grp | 2);
    float iv1 = __shfl_sync(0xffffffffu, iv, grp | 1);
    float iv2 = __shfl_sync(0xffffffffu, iv, grp | 2);

    if (q == 0) {
        float p0 = pts[n*3 + 0], p1 = pts[n*3 + 1], p2 = pts[n*3 + 2];
        // block0 words 0..7 = pairs k {0,8,2,10,4,12,6,14}
        uint4 h0 = make_uint4(pack_h2(p0, p1), pack_h2(iv2, 0.f),
                              pack_h2(p2, im), 0u);
        uint4 h1 = make_uint4(pack_h2(im1, im2), 0u,
                              pack_h2(iv, iv1), 0u);
        uint4 l0 = make_uint4(pack_lo2(p0, p1), pack_lo2(iv2, 0.f),
                              pack_lo2(p2, im), 0u);
        uint4 l1 = make_uint4(pack_lo2(im1, im2), 0u,
                              pack_lo2(iv, iv1), 0u);
        *(uint4*)(rowH + 0) = h0;
        *(uint4*)(rowH + 4) = h1;
        *(uint4*)(rowL + 0) = l0;
        *(uint4*)(rowL + 4) = l1;
    }
}

// ---------------- MLP kernel: 4 warps x M32, A in regs, B in smem, N in 4 quarters ----
#define MLP_GRID 296
#define MLP_SMEM (B_WORDS*4 + HID*8)

__global__ __launch_bounds__(128, 2)
void mlp_kernel(const float* __restrict__ b1, const float* __restrict__ W2,
                const float* __restrict__ b2, float* __restrict__ out) {
    extern __shared__ uint32_t sm[];
    uint32_t* Bs0 = sm;                  // hi plane [256][44]
    uint32_t* Bs1 = sm + HID*WROW;       // lo plane
    float2*  bwS  = (float2*)(sm + B_WORDS);

    int tid = threadIdx.x;
    int l = tid & 31, w = tid >> 5;
    int g = l >> 2, t4 = l & 3;

    {
        const uint4* src = (const uint4*)g_B;
        uint4* dst = (uint4*)sm;
#pragma unroll 4
        for (int i = tid; i < B_WORDS/4; i += 128) dst[i] = src[i];
        for (int i = tid; i < HID; i += 128) bwS[i] = make_float2(b1[i], W2[i]);
    }
    __syncthreads();

    float b2v = b2[0];

    for (int t = blockIdx.x; t < MTOT/128; t += gridDim.x) {
        int m0 = t*128 + w*32;

        // load A fragments into registers: [mt][s5][rowhalf] hi/lo
        uint2 aH[2][NK16][2], aL[2][NK16][2];
#pragma unroll
        for (int mt = 0; mt < 2; mt++) {
            int r0 = m0 + mt*16 + g;
#pragma unroll
            for (int s5 = 0; s5 < NK16; s5++)
#pragma unroll
                for (int rh = 0; rh < 2; rh++) {
                    size_t off = (size_t)(r0 + 8*rh)*AROW + s5*8 + 2*t4;
                    aH[mt][s5][rh] = *(const uint2*)(g_A + off);
                    aL[mt][s5][rh] = *(const uint2*)(g_A + (size_t)MTOT*AROW + off);
                }
        }

        float zp[2][2] = {{0.f,0.f},{0.f,0.f}};   // [mt][rowhalf]

#pragma unroll
        for (int nq = 0; nq < 4; nq++) {
            float acc[2][8][4];
#pragma unroll
            for (int mt = 0; mt < 2; mt++)
#pragma unroll
                for (int j = 0; j < 8; j++)
#pragma unroll
                    for (int c = 0; c < 4; c++) acc[mt][j][c] = 0.f;

#pragma unroll
            for (int s5 = 0; s5 < NK16; s5++) {
#pragma unroll
                for (int j = 0; j < 8; j++) {
                    int nr = nq*64 + j*8 + g;
                    int ob = nr*WROW + s5*8 + 2*t4;
                    uint2 bh = *(const uint2*)(Bs0 + ob);
                    uint2 bl = *(const uint2*)(Bs1 + ob);
#pragma unroll
                    for (int mt = 0; mt < 2; mt++) {
                        MMA16816(acc[mt][j], aH[mt][s5][0].x, aH[mt][s5][1].x,
                                 aH[mt][s5][0].y, aH[mt][s5][1].y, bh.x, bh.y);
                        MMA16816(acc[mt][j], aL[mt][s5][0].x, aL[mt][s5][1].x,
                                 aL[mt][s5][0].y, aL[mt][s5][1].y, bh.x, bh.y);
                        MMA16816(acc[mt][j], aH[mt][s5][0].x, aH[mt][s5][1].x,
                                 aH[mt][s5][0].y, aH[mt][s5][1].y, bl.x, bl.y);
                    }
                }
            }
            // partial epilogue for this N-quarter
#pragma unroll
            for (int j = 0; j < 8; j++) {
                int c0 = nq*64 + j*8 + 2*t4;
                float2 bw0 = bwS[c0];
                float2 bw1 = bwS[c0 + 1];
#pragma unroll
                for (int mt = 0; mt < 2; mt++) {
                    zp[mt][0] += fmaxf(acc[mt][j][0] + bw0.x, 0.f) * bw0.y
                               + fmaxf(acc[mt][j][1] + bw1.x, 0.f) * bw1.y;
                    zp[mt][1] += fmaxf(acc[mt][j][2] + bw0.x, 0.f) * bw0.y
                               + fmaxf(acc[mt][j][3] + bw1.x, 0.f) * bw1.y;
                }
            }
        }

        // reduce over the 4 t4 lanes, write 16 rows per warp-half
#pragma unroll
        for (int mt = 0; mt < 2; mt++)
#pragma unroll
            for (int rh = 0; rh < 2; rh++) {
                float z = zp[mt][rh];
                z += __shfl_xor_sync(0xffffffffu, z, 1);
                z += __shfl_xor_sync(0xffffffffu, z, 2);
                if (t4 == 0) {
                    float zz = z + b2v;
                    // 1 - exp(-softplus(zz)) == sigmoid(zz)
                    out[m0 + mt*16 + rh*8 + g] = 1.f / (1.f + expf(-zz));
                }
            }
    }
}

// ---------------- launch ----------------
extern "C" void kernel_launch(void* const* d_in, const int* in_sizes, int n_in,
                              void* d_out, int out_size) {
    const float* imgs  = (const float*)d_in[0];
    const float* feats = (const float*)d_in[1];
    const float* grid  = (const float*)d_in[2];
    const float* pts   = (const float*)d_in[3];
    const float* W1    = (const float*)d_in[4];
    const float* b1    = (const float*)d_in[5];
    const float* W2    = (const float*)d_in[6];
    const float* b2    = (const float*)d_in[7];
    float* out = (float*)d_out;

    cudaFuncSetAttribute(mlp_kernel, cudaFuncAttributeMaxDynamicSharedMemorySize, MLP_SMEM);

    prep_B<<<(HID*40 + 255)/256, 256>>>(W1);
    transpose_imgs<<<(NVIEW*BATCH*HWI + 255)/256, 256>>>(imgs);
    transpose_feats<<<dim3(HWF/32, NVIEW*BATCH), dim3(32, 32)>>>(feats);
    gather_kernel<<<MTOT/16, 256>>>(grid, pts);
    mlp_kernel<<<MLP_GRID, 128, MLP_SMEM>>>(b1, W2, b2, out);
}

// round 11
// speedup vs baseline: 1.4540x; 1.1333x over previous
#include <cuda_runtime.h>
#include <cuda_fp16.h>
#include <math.h>
#include <stdint.h>

#define NVIEW 5
#define NBINS 128000
#define BATCH 2
#define HF 128
#define WF 128
#define HWF (HF*WF)
#define HI 512
#define WI 512
#define HWI (HI*WI)
#define CF 32
#define HID 256
#define INDIM 73
#define MTOT (BATCH*NBINS)     // 256000

#define NK16 5
#define AROW 40                 // words per A row in global
#define WROW 44                 // words per B row in smem (bank-padded)
#define B_WORDS (2*HID*WROW)

// ---------------- scratch (device globals: allocation-free, zero-initialized) -------
// +pad entries so unconditional x0+1 / y0+1 corner reads never leave the array.
__device__ float4   g_imgs_t[NVIEW*BATCH*HWI + 600];
__device__ float4   g_feats_t[NVIEW*BATCH*HWF*(CF/4) + 4200];
__device__ uint32_t g_B[B_WORDS];
__device__ uint32_t g_A[2*MTOT*AROW];

__device__ __host__ constexpr int word_of(int k) {
    return 8*(k >> 4) + (((k & 15) < 8) ? (k & 15) : ((k & 15) - 7));
}
__device__ __forceinline__ int orig_of(int c) {
    int blk = c >> 4, i = c & 15;
    if (blk == 0) {
        if (i < 3) return i;
        if (i < 6) return 3 + (i - 3);
        if (i < 9) return 38 + (i - 6);
        return -1;
    }
    int cg = blk - 1;
    if (i < 8) return 6 + 8*cg + i;
    return 41 + 8*cg + (i - 8);
}
__device__ __forceinline__ uint32_t pack_h2(float a, float b) {
    __half ha = __float2half_rn(a), hb = __float2half_rn(b);
    return (uint32_t)__half_as_ushort(ha) | ((uint32_t)__half_as_ushort(hb) << 16);
}
__device__ __forceinline__ uint32_t pack_lo2(float a, float b) {
    __half ha = __float2half_rn(a), hb = __float2half_rn(b);
    return pack_h2(a - __half2float(ha), b - __half2float(hb));
}

#define MMA16816(d, a0, a1, a2, a3, b0, b1) \
    asm volatile("mma.sync.aligned.m16n8k16.row.col.f32.f16.f16.f32 " \
        "{%0,%1,%2,%3}, {%4,%5,%6,%7}, {%8,%9}, {%0,%1,%2,%3};" \
        : "+f"((d)[0]), "+f"((d)[1]), "+f"((d)[2]), "+f"((d)[3]) \
        : "r"(a0), "r"(a1), "r"(a2), "r"(a3), "r"(b0), "r"(b1))

// ---------------- prep W1 ----------------
__global__ void prep_B(const float* __restrict__ W1) {
    int i = blockIdx.x * 256 + threadIdx.x;
    if (i >= HID * 40) return;
    int n = i / 40;
    int k = (i - n * 40) * 2;
    int o0 = orig_of(k), o1 = orig_of(k + 1);
    float v0 = (o0 >= 0) ? W1[o0 * HID + n] : 0.f;
    float v1 = (o1 >= 0) ? W1[o1 * HID + n] : 0.f;
    int w = word_of(k);
    g_B[n * WROW + w] = pack_h2(v0, v1);
    g_B[HID * WROW + n * WROW + w] = pack_lo2(v0, v1);
}

// ---------------- layout transposes ----------------
__global__ void transpose_imgs(const float* __restrict__ im) {
    int idx = blockIdx.x * blockDim.x + threadIdx.x;
    if (idx >= NVIEW*BATCH*HWI) return;
    int vb = idx >> 18;
    int p  = idx & (HWI - 1);
    const float* base = im + (size_t)vb * 3 * HWI + p;
    g_imgs_t[idx] = make_float4(base[0], base[HWI], base[2*HWI], 0.f);
}
__global__ void transpose_feats(const float* __restrict__ f) {
    __shared__ float tile[32][33];
    int vb = blockIdx.y;
    int p0 = blockIdx.x * 32;
    int tx = threadIdx.x, ty = threadIdx.y;
    tile[ty][tx] = f[((size_t)vb*CF + ty) * HWF + p0 + tx];
    __syncthreads();
    ((float*)g_feats_t)[((size_t)vb*HWF + p0 + ty) * CF + tx] = tile[tx][ty];
}

// ---------------- gather: 2 pts/warp, lane=channel-pair, slim addressing ----------
__global__ __launch_bounds__(256)
void gather_kernel(const float* __restrict__ grid_, const float* __restrict__ pts) {
    int tid = blockIdx.x * 256 + threadIdx.x;
    int l   = threadIdx.x & 31;
    int q   = l & 15;
    int m   = (tid >> 5) * 2 + (l >> 4);
    int b   = (m >= NBINS) ? 1 : 0;
    int n   = m - b * NBINS;

    float2 s2  = make_float2(0.f, 0.f), ss2 = make_float2(0.f, 0.f);
    float  si = 0.f, ssi = 0.f;

#pragma unroll
    for (int v = 0; v < NVIEW; v++) {
        float2 g = *(const float2*)(grid_ + ((size_t)v*NBINS + n)*2);

        // ---- feats (128x128): no clamps needed, corners via imm offsets ----
        {
            float fx = fmaf(g.x, 63.5f, 63.5f);
            float fy = fmaf(g.y, 63.5f, 63.5f);
            int x0 = (int)fx, y0 = (int)fy;
            float wx1 = fx - (float)x0, wy1 = fy - (float)y0;
            float wx0 = 1.f - wx1, wy0 = 1.f - wy1;
            float w00 = wx0*wy0, w01 = wx1*wy0, w10 = wx0*wy1, w11 = wx1*wy1;
            int pix = (v*BATCH + b) * HWF + y0*WF + x0;
            const char* p = (const char*)g_feats_t + (size_t)pix*128 + q*8;
            float2 p00 = *(const float2*)(p);
            float2 p01 = *(const float2*)(p + 128);
            float2 p10 = *(const float2*)(p + WF*128);
            float2 p11 = *(const float2*)(p + WF*128 + 128);
            float vx = w00*p00.x + w01*p01.x + w10*p10.x + w11*p11.x;
            float vy = w00*p00.y + w01*p01.y + w10*p10.y + w11*p11.y;
            s2.x += vx; ss2.x += vx*vx;
            s2.y += vy; ss2.y += vy*vy;
        }
        // ---- imgs (512x512), channel q (q<3) ----
        {
            float fx = fmaf(g.x, 255.5f, 255.5f);
            float fy = fmaf(g.y, 255.5f, 255.5f);
            int x0 = (int)fx, y0 = (int)fy;
            float wx1 = fx - (float)x0, wy1 = fy - (float)y0;
            float wx0 = 1.f - wx1, wy0 = 1.f - wy1;
            float w00 = wx0*wy0, w01 = wx1*wy0, w10 = wx0*wy1, w11 = wx1*wy1;
            int pix = (v*BATCH + b) * HWI + y0*WI + x0;
            const char* p = (const char*)g_imgs_t + (size_t)pix*16 + q*4;
            float vv = 0.f;
            if (q < 3) {
                float p00 = *(const float*)(p);
                float p01 = *(const float*)(p + 16);
                float p10 = *(const float*)(p + WI*16);
                float p11 = *(const float*)(p + WI*16 + 16);
                vv = w00*p00 + w01*p01 + w10*p10 + w11*p11;
            }
            si += vv; ssi += vv*vv;
        }
    }

    float mean0 = s2.x * 0.2f, mean1 = s2.y * 0.2f;
    float ev0 = __expf(-fmaxf(ss2.x * 0.2f - mean0*mean0, 0.f));
    float ev1 = __expf(-fmaxf(ss2.y * 0.2f - mean1*mean1, 0.f));
    float im  = si * 0.2f;
    float iv  = __expf(-fmaxf(ssi * 0.2f - im*im, 0.f));

    uint32_t* rowH = g_A + (size_t)m * AROW;
    uint32_t* rowL = g_A + (size_t)(MTOT + m) * AROW;

    {
        int wslot = 8*(1 + (q >> 2)) + 2*(q & 3);
        *(uint2*)(rowH + wslot) = make_uint2(pack_h2(mean0, mean1), pack_h2(ev0, ev1));
        *(uint2*)(rowL + wslot) = make_uint2(pack_lo2(mean0, mean1), pack_lo2(ev0, ev1));
    }

    unsigned grp = (unsigned)(l & 16);
    float im1 = __shfl_sync(0xffffffffu, im, grp | 1);
    float im2 = __shfl_sync(0xffffffffu, im, grp | 2);
    float iv1 = __shfl_sync(0xffffffffu, iv, grp | 1);
    float iv2 = __shfl_sync(0xffffffffu, iv, grp | 2);

    if (q == 0) {
        float p0 = pts[n*3 + 0], p1 = pts[n*3 + 1], p2 = pts[n*3 + 2];
        // block0 words 0..7 = k-pairs {0,8,2,10,4,12,6,14}
        *(uint4*)(rowH + 0) = make_uint4(pack_h2(p0, p1), pack_h2(iv2, 0.f),
                                         pack_h2(p2, im), 0u);
        *(uint4*)(rowH + 4) = make_uint4(pack_h2(im1, im2), 0u,
                                         pack_h2(iv, iv1), 0u);
        *(uint4*)(rowL + 0) = make_uint4(pack_lo2(p0, p1), pack_lo2(iv2, 0.f),
                                         pack_lo2(p2, im), 0u);
        *(uint4*)(rowL + 4) = make_uint4(pack_lo2(im1, im2), 0u,
                                         pack_lo2(iv, iv1), 0u);
    }
}

// ---------------- MLP: 4 warps x M32, pass-separated HMMA (RAW distance 16) --------
#define MLP_GRID 296
#define MLP_SMEM (B_WORDS*4 + HID*8)

__global__ __launch_bounds__(128, 2)
void mlp_kernel(const float* __restrict__ b1, const float* __restrict__ W2,
                const float* __restrict__ b2, float* __restrict__ out) {
    extern __shared__ uint32_t sm[];
    uint32_t* Bs0 = sm;
    uint32_t* Bs1 = sm + HID*WROW;
    float2*  bwS  = (float2*)(sm + B_WORDS);

    int tid = threadIdx.x;
    int l = tid & 31, w = tid >> 5;
    int g = l >> 2, t4 = l & 3;

    {
        const uint4* src = (const uint4*)g_B;
        uint4* dst = (uint4*)sm;
#pragma unroll 4
        for (int i = tid; i < B_WORDS/4; i += 128) dst[i] = src[i];
        for (int i = tid; i < HID; i += 128) bwS[i] = make_float2(b1[i], W2[i]);
    }
    __syncthreads();

    float b2v = b2[0];

    for (int t = blockIdx.x; t < MTOT/128; t += gridDim.x) {
        int m0 = t*128 + w*32;

        uint2 aH[2][NK16][2], aL[2][NK16][2];
#pragma unroll
        for (int mt = 0; mt < 2; mt++) {
            int r0 = m0 + mt*16 + g;
#pragma unroll
            for (int s5 = 0; s5 < NK16; s5++)
#pragma unroll
                for (int rh = 0; rh < 2; rh++) {
                    size_t off = (size_t)(r0 + 8*rh)*AROW + s5*8 + 2*t4;
                    aH[mt][s5][rh] = *(const uint2*)(g_A + off);
                    aL[mt][s5][rh] = *(const uint2*)(g_A + (size_t)MTOT*AROW + off);
                }
        }

        float zp[2][2] = {{0.f,0.f},{0.f,0.f}};

#pragma unroll
        for (int nq = 0; nq < 4; nq++) {
            float acc[2][8][4];
#pragma unroll
            for (int mt = 0; mt < 2; mt++)
#pragma unroll
                for (int j = 0; j < 8; j++)
#pragma unroll
                    for (int c = 0; c < 4; c++) acc[mt][j][c] = 0.f;

#pragma unroll
            for (int s5 = 0; s5 < NK16; s5++) {
                uint2 bh[8], bl[8];
#pragma unroll
                for (int j = 0; j < 8; j++) {
                    int ob = (nq*64 + j*8 + g)*WROW + s5*8 + 2*t4;
                    bh[j] = *(const uint2*)(Bs0 + ob);
                    bl[j] = *(const uint2*)(Bs1 + ob);
                }
                // pass 0: Ahi x Bhi — each acc touched once per sweep
#pragma unroll
                for (int j = 0; j < 8; j++)
#pragma unroll
                    for (int mt = 0; mt < 2; mt++)
                        MMA16816(acc[mt][j], aH[mt][s5][0].x, aH[mt][s5][1].x,
                                 aH[mt][s5][0].y, aH[mt][s5][1].y, bh[j].x, bh[j].y);
                // pass 1: Alo x Bhi
#pragma unroll
                for (int j = 0; j < 8; j++)
#pragma unroll
                    for (int mt = 0; mt < 2; mt++)
                        MMA16816(acc[mt][j], aL[mt][s5][0].x, aL[mt][s5][1].x,
                                 aL[mt][s5][0].y, aL[mt][s5][1].y, bh[j].x, bh[j].y);
                // pass 2: Ahi x Blo
#pragma unroll
                for (int j = 0; j < 8; j++)
#pragma unroll
                    for (int mt = 0; mt < 2; mt++)
                        MMA16816(acc[mt][j], aH[mt][s5][0].x, aH[mt][s5][1].x,
                                 aH[mt][s5][0].y, aH[mt][s5][1].y, bl[j].x, bl[j].y);
            }
#pragma unroll
            for (int j = 0; j < 8; j++) {
                int c0 = nq*64 + j*8 + 2*t4;
                float2 bw0 = bwS[c0];
                float2 bw1 = bwS[c0 + 1];
#pragma unroll
                for (int mt = 0; mt < 2; mt++) {
                    zp[mt][0] += fmaxf(acc[mt][j][0] + bw0.x, 0.f) * bw0.y
                               + fmaxf(acc[mt][j][1] + bw1.x, 0.f) * bw1.y;
                    zp[mt][1] += fmaxf(acc[mt][j][2] + bw0.x, 0.f) * bw0.y
                               + fmaxf(acc[mt][j][3] + bw1.x, 0.f) * bw1.y;
                }
            }
        }

#pragma unroll
        for (int mt = 0; mt < 2; mt++)
#pragma unroll
            for (int rh = 0; rh < 2; rh++) {
                float z = zp[mt][rh];
                z += __shfl_xor_sync(0xffffffffu, z, 1);
                z += __shfl_xor_sync(0xffffffffu, z, 2);
                if (t4 == 0) {
                    float zz = z + b2v;
                    // 1 - exp(-softplus(zz)) == sigmoid(zz)
                    out[m0 + mt*16 + rh*8 + g] = 1.f / (1.f + expf(-zz));
                }
            }
    }
}

// ---------------- launch ----------------
extern "C" void kernel_launch(void* const* d_in, const int* in_sizes, int n_in,
                              void* d_out, int out_size) {
    const float* imgs  = (const float*)d_in[0];
    const float* feats = (const float*)d_in[1];
    const float* grid  = (const float*)d_in[2];
    const float* pts   = (const float*)d_in[3];
    const float* W1    = (const float*)d_in[4];
    const float* b1    = (const float*)d_in[5];
    const float* W2    = (const float*)d_in[6];
    const float* b2    = (const float*)d_in[7];
    float* out = (float*)d_out;

    cudaFuncSetAttribute(mlp_kernel, cudaFuncAttributeMaxDynamicSharedMemorySize, MLP_SMEM);

    prep_B<<<(HID*40 + 255)/256, 256>>>(W1);
    transpose_imgs<<<(NVIEW*BATCH*HWI + 255)/256, 256>>>(imgs);
    transpose_feats<<<dim3(HWF/32, NVIEW*BATCH), dim3(32, 32)>>>(feats);
    gather_kernel<<<MTOT/16, 256>>>(grid, pts);
    mlp_kernel<<<MLP_GRID, 128, MLP_SMEM>>>(b1, W2, b2, out);
}

// round 12
// speedup vs baseline: 1.5962x; 1.0978x over previous
#include <cuda_runtime.h>
#include <cuda_fp16.h>
#include <math.h>
#include <stdint.h>

#define NVIEW 5
#define NBINS 128000
#define BATCH 2
#define HF 128
#define WF 128
#define HWF (HF*WF)
#define HI 512
#define WI 512
#define HWI (HI*WI)
#define CF 32
#define HID 256
#define INDIM 73
#define MTOT (BATCH*NBINS)     // 256000

#define NK16 5
#define AROW 40                 // words per A row in global
#define WROW 44                 // words per B row in smem (bank-padded)
#define B_WORDS (HID*WROW)      // hi plane only

// ---------------- scratch (device globals: allocation-free, zero-initialized) -------
// +pad entries so unconditional x0+1 / y0+1 corner reads never leave the array.
__device__ float4   g_imgs_t[NVIEW*BATCH*HWI + 600];
__device__ float4   g_feats_t[NVIEW*BATCH*HWF*(CF/4) + 4200];
__device__ uint32_t g_B[B_WORDS];
__device__ uint32_t g_A[2*MTOT*AROW];   // hi plane then lo plane

__device__ __host__ constexpr int word_of(int k) {
    return 8*(k >> 4) + (((k & 15) < 8) ? (k & 15) : ((k & 15) - 7));
}
__device__ __forceinline__ int orig_of(int c) {
    int blk = c >> 4, i = c & 15;
    if (blk == 0) {
        if (i < 3) return i;
        if (i < 6) return 3 + (i - 3);
        if (i < 9) return 38 + (i - 6);
        return -1;
    }
    int cg = blk - 1;
    if (i < 8) return 6 + 8*cg + i;
    return 41 + 8*cg + (i - 8);
}
__device__ __forceinline__ uint32_t pack_h2(float a, float b) {
    __half ha = __float2half_rn(a), hb = __float2half_rn(b);
    return (uint32_t)__half_as_ushort(ha) | ((uint32_t)__half_as_ushort(hb) << 16);
}
__device__ __forceinline__ uint32_t pack_lo2(float a, float b) {
    __half ha = __float2half_rn(a), hb = __float2half_rn(b);
    return pack_h2(a - __half2float(ha), b - __half2float(hb));
}

#define MMA16816(d, a0, a1, a2, a3, b0, b1) \
    asm volatile("mma.sync.aligned.m16n8k16.row.col.f32.f16.f16.f32 " \
        "{%0,%1,%2,%3}, {%4,%5,%6,%7}, {%8,%9}, {%0,%1,%2,%3};" \
        : "+f"((d)[0]), "+f"((d)[1]), "+f"((d)[2]), "+f"((d)[3]) \
        : "r"(a0), "r"(a1), "r"(a2), "r"(a3), "r"(b0), "r"(b1))

// ---------------- prep W1 (hi plane only — Blo pass dropped) ----------------
__global__ void prep_B(const float* __restrict__ W1) {
    int i = blockIdx.x * 256 + threadIdx.x;
    if (i >= HID * 40) return;
    int n = i / 40;
    int k = (i - n * 40) * 2;
    int o0 = orig_of(k), o1 = orig_of(k + 1);
    float v0 = (o0 >= 0) ? W1[o0 * HID + n] : 0.f;
    float v1 = (o1 >= 0) ? W1[o1 * HID + n] : 0.f;
    g_B[n * WROW + word_of(k)] = pack_h2(v0, v1);
}

// ---------------- layout transposes ----------------
__global__ void transpose_imgs(const float* __restrict__ im) {
    int idx = blockIdx.x * blockDim.x + threadIdx.x;
    if (idx >= NVIEW*BATCH*HWI) return;
    int vb = idx >> 18;
    int p  = idx & (HWI - 1);
    const float* base = im + (size_t)vb * 3 * HWI + p;
    g_imgs_t[idx] = make_float4(base[0], base[HWI], base[2*HWI], 0.f);
}
__global__ void transpose_feats(const float* __restrict__ f) {
    __shared__ float tile[32][33];
    int vb = blockIdx.y;
    int p0 = blockIdx.x * 32;
    int tx = threadIdx.x, ty = threadIdx.y;
    tile[ty][tx] = f[((size_t)vb*CF + ty) * HWF + p0 + tx];
    __syncthreads();
    ((float*)g_feats_t)[((size_t)vb*HWF + p0 + ty) * CF + tx] = tile[tx][ty];
}

// ---------------- gather: 4 pts/warp, 8 lanes/pt, lane = channel-quad ----------
__global__ __launch_bounds__(256)
void gather_kernel(const float* __restrict__ grid_, const float* __restrict__ pts) {
    int tid = blockIdx.x * 256 + threadIdx.x;
    int q   = tid & 7;                   // channel-quad: feat chans 4q..4q+3
    int m   = tid >> 3;
    int b   = (m >= NBINS) ? 1 : 0;
    int n   = m - b * NBINS;

    float4 s4  = make_float4(0.f,0.f,0.f,0.f), ss4 = make_float4(0.f,0.f,0.f,0.f);
    float3 si  = make_float3(0.f,0.f,0.f),  ssi = make_float3(0.f,0.f,0.f);

#pragma unroll
    for (int v = 0; v < NVIEW; v++) {
        float2 g = *(const float2*)(grid_ + ((size_t)v*NBINS + n)*2);

        // ---- feats (128x128), 4 channels per lane via LDG.128 ----
        {
            float fx = fmaf(g.x, 63.5f, 63.5f);
            float fy = fmaf(g.y, 63.5f, 63.5f);
            int x0 = (int)fx, y0 = (int)fy;
            float wx1 = fx - (float)x0, wy1 = fy - (float)y0;
            float wx0 = 1.f - wx1, wy0 = 1.f - wy1;
            float w00 = wx0*wy0, w01 = wx1*wy0, w10 = wx0*wy1, w11 = wx1*wy1;
            int pix = (v*BATCH + b) * HWF + y0*WF + x0;
            const char* p = (const char*)g_feats_t + (size_t)pix*128 + q*16;
            float4 p00 = *(const float4*)(p);
            float4 p01 = *(const float4*)(p + 128);
            float4 p10 = *(const float4*)(p + WF*128);
            float4 p11 = *(const float4*)(p + WF*128 + 128);
            float t;
            t = w00*p00.x + w01*p01.x + w10*p10.x + w11*p11.x; s4.x += t; ss4.x += t*t;
            t = w00*p00.y + w01*p01.y + w10*p10.y + w11*p11.y; s4.y += t; ss4.y += t*t;
            t = w00*p00.z + w01*p01.z + w10*p10.z + w11*p11.z; s4.z += t; ss4.z += t*t;
            t = w00*p00.w + w01*p01.w + w10*p10.w + w11*p11.w; s4.w += t; ss4.w += t*t;
        }
        // ---- imgs (512x512): only lane q==0 of each point does all 3 channels ----
        if (q == 0) {
            float fx = fmaf(g.x, 255.5f, 255.5f);
            float fy = fmaf(g.y, 255.5f, 255.5f);
            int x0 = (int)fx, y0 = (int)fy;
            float wx1 = fx - (float)x0, wy1 = fy - (float)y0;
            float wx0 = 1.f - wx1, wy0 = 1.f - wy1;
            float w00 = wx0*wy0, w01 = wx1*wy0, w10 = wx0*wy1, w11 = wx1*wy1;
            int pix = (v*BATCH + b) * HWI + y0*WI + x0;
            const char* p = (const char*)g_imgs_t + (size_t)pix*16;
            float4 p00 = *(const float4*)(p);
            float4 p01 = *(const float4*)(p + 16);
            float4 p10 = *(const float4*)(p + WI*16);
            float4 p11 = *(const float4*)(p + WI*16 + 16);
            float t;
            t = w00*p00.x + w01*p01.x + w10*p10.x + w11*p11.x; si.x += t; ssi.x += t*t;
            t = w00*p00.y + w01*p01.y + w10*p10.y + w11*p11.y; si.y += t; ssi.y += t*t;
            t = w00*p00.z + w01*p01.z + w10*p10.z + w11*p11.z; si.z += t; ssi.z += t*t;
        }
    }

    uint32_t* rowH = g_A + (size_t)m * AROW;
    uint32_t* rowL = g_A + (size_t)(MTOT + m) * AROW;

    // feat epilogue: 4 channels -> one uint4 per plane
    {
        float m0 = s4.x*0.2f, m1 = s4.y*0.2f, m2 = s4.z*0.2f, m3 = s4.w*0.2f;
        float v0 = __expf(-fmaxf(ss4.x*0.2f - m0*m0, 0.f));
        float v1 = __expf(-fmaxf(ss4.y*0.2f - m1*m1, 0.f));
        float v2 = __expf(-fmaxf(ss4.z*0.2f - m2*m2, 0.f));
        float v3 = __expf(-fmaxf(ss4.w*0.2f - m3*m3, 0.f));
        int wslot = 8*(1 + (q >> 1)) + 4*(q & 1);
        *(uint4*)(rowH + wslot) = make_uint4(pack_h2(m0, m1), pack_h2(v0, v1),
                                             pack_h2(m2, m3), pack_h2(v2, v3));
        *(uint4*)(rowL + wslot) = make_uint4(pack_lo2(m0, m1), pack_lo2(v0, v1),
                                             pack_lo2(m2, m3), pack_lo2(v2, v3));
    }

    // block0 (pts + img stats) entirely in lane q==0 — no shuffles
    if (q == 0) {
        float im0 = si.x*0.2f, im1 = si.y*0.2f, im2 = si.z*0.2f;
        float iv0 = __expf(-fmaxf(ssi.x*0.2f - im0*im0, 0.f));
        float iv1 = __expf(-fmaxf(ssi.y*0.2f - im1*im1, 0.f));
        float iv2 = __expf(-fmaxf(ssi.z*0.2f - im2*im2, 0.f));
        float p0 = pts[n*3 + 0], p1 = pts[n*3 + 1], p2 = pts[n*3 + 2];
        // block0 words: pairs (0,1)->w0 (2,3)->w2 (4,5)->w4 (6,7)->w6 (8,9)->w1
        *(uint4*)(rowH + 0) = make_uint4(pack_h2(p0, p1), pack_h2(iv2, 0.f),
                                         pack_h2(p2, im0), 0u);
        *(uint4*)(rowH + 4) = make_uint4(pack_h2(im1, im2), 0u,
                                         pack_h2(iv0, iv1), 0u);
        *(uint4*)(rowL + 0) = make_uint4(pack_lo2(p0, p1), pack_lo2(iv2, 0.f),
                                         pack_lo2(p2, im0), 0u);
        *(uint4*)(rowL + 4) = make_uint4(pack_lo2(im1, im2), 0u,
                                         pack_lo2(iv0, iv1), 0u);
    }
}

// ---------------- MLP: 2-pass fp16-split (AhiBhi + AloBhi), 3 CTAs/SM ------------
#define MLP_GRID 444
#define MLP_SMEM (B_WORDS*4 + HID*8)

__global__ __launch_bounds__(128, 3)
void mlp_kernel(const float* __restrict__ b1, const float* __restrict__ W2,
                const float* __restrict__ b2, float* __restrict__ out) {
    extern __shared__ uint32_t sm[];
    uint32_t* Bs0 = sm;                  // hi plane [256][44]
    float2*  bwS  = (float2*)(sm + B_WORDS);

    int tid = threadIdx.x;
    int l = tid & 31, w = tid >> 5;
    int g = l >> 2, t4 = l & 3;

    {
        const uint4* src = (const uint4*)g_B;
        uint4* dst = (uint4*)sm;
#pragma unroll 4
        for (int i = tid; i < B_WORDS/4; i += 128) dst[i] = src[i];
        for (int i = tid; i < HID; i += 128) bwS[i] = make_float2(b1[i], W2[i]);
    }
    __syncthreads();

    float b2v = b2[0];

    for (int t = blockIdx.x; t < MTOT/128; t += gridDim.x) {
        int m0 = t*128 + w*32;

        uint2 aH[2][NK16][2], aL[2][NK16][2];
#pragma unroll
        for (int mt = 0; mt < 2; mt++) {
            int r0 = m0 + mt*16 + g;
#pragma unroll
            for (int s5 = 0; s5 < NK16; s5++)
#pragma unroll
                for (int rh = 0; rh < 2; rh++) {
                    size_t off = (size_t)(r0 + 8*rh)*AROW + s5*8 + 2*t4;
                    aH[mt][s5][rh] = *(const uint2*)(g_A + off);
                    aL[mt][s5][rh] = *(const uint2*)(g_A + (size_t)MTOT*AROW + off);
                }
        }

        float zp[2][2] = {{0.f,0.f},{0.f,0.f}};

#pragma unroll
        for (int nq = 0; nq < 4; nq++) {
            float acc[2][8][4];
#pragma unroll
            for (int mt = 0; mt < 2; mt++)
#pragma unroll
                for (int j = 0; j < 8; j++)
#pragma unroll
                    for (int c = 0; c < 4; c++) acc[mt][j][c] = 0.f;

#pragma unroll
            for (int s5 = 0; s5 < NK16; s5++) {
                uint2 bh[8];
#pragma unroll
                for (int j = 0; j < 8; j++) {
                    int ob = (nq*64 + j*8 + g)*WROW + s5*8 + 2*t4;
                    bh[j] = *(const uint2*)(Bs0 + ob);
                }
                // pass 0: Ahi x Bhi
#pragma unroll
                for (int j = 0; j < 8; j++)
#pragma unroll
                    for (int mt = 0; mt < 2; mt++)
                        MMA16816(acc[mt][j], aH[mt][s5][0].x, aH[mt][s5][1].x,
                                 aH[mt][s5][0].y, aH[mt][s5][1].y, bh[j].x, bh[j].y);
                // pass 1: Alo x Bhi
#pragma unroll
                for (int j = 0; j < 8; j++)
#pragma unroll
                    for (int mt = 0; mt < 2; mt++)
                        MMA16816(acc[mt][j], aL[mt][s5][0].x, aL[mt][s5][1].x,
                                 aL[mt][s5][0].y, aL[mt][s5][1].y, bh[j].x, bh[j].y);
            }
#pragma unroll
            for (int j = 0; j < 8; j++) {
                int c0 = nq*64 + j*8 + 2*t4;
                float2 bw0 = bwS[c0];
                float2 bw1 = bwS[c0 + 1];
#pragma unroll
                for (int mt = 0; mt < 2; mt++) {
                    zp[mt][0] += fmaxf(acc[mt][j][0] + bw0.x, 0.f) * bw0.y
                               + fmaxf(acc[mt][j][1] + bw1.x, 0.f) * bw1.y;
                    zp[mt][1] += fmaxf(acc[mt][j][2] + bw0.x, 0.f) * bw0.y
                               + fmaxf(acc[mt][j][3] + bw1.x, 0.f) * bw1.y;
                }
            }
        }

#pragma unroll
        for (int mt = 0; mt < 2; mt++)
#pragma unroll
            for (int rh = 0; rh < 2; rh++) {
                float z = zp[mt][rh];
                z += __shfl_xor_sync(0xffffffffu, z, 1);
                z += __shfl_xor_sync(0xffffffffu, z, 2);
                if (t4 == 0) {
                    float zz = z + b2v;
                    // 1 - exp(-softplus(zz)) == sigmoid(zz)
                    out[m0 + mt*16 + rh*8 + g] = 1.f / (1.f + expf(-zz));
                }
            }
    }
}

// ---------------- launch ----------------
extern "C" void kernel_launch(void* const* d_in, const int* in_sizes, int n_in,
                              void* d_out, int out_size) {
    const float* imgs  = (const float*)d_in[0];
    const float* feats = (const float*)d_in[1];
    const float* grid  = (const float*)d_in[2];
    const float* pts   = (const float*)d_in[3];
    const float* W1    = (const float*)d_in[4];
    const float* b1    = (const float*)d_in[5];
    const float* W2    = (const float*)d_in[6];
    const float* b2    = (const float*)d_in[7];
    float* out = (float*)d_out;

    cudaFuncSetAttribute(mlp_kernel, cudaFuncAttributeMaxDynamicSharedMemorySize, MLP_SMEM);

    prep_B<<<(HID*40 + 255)/256, 256>>>(W1);
    transpose_imgs<<<(NVIEW*BATCH*HWI + 255)/256, 256>>>(imgs);
    transpose_feats<<<dim3(HWF/32, NVIEW*BATCH), dim3(32, 32)>>>(feats);
    gather_kernel<<<MTOT/32, 256>>>(grid, pts);
    mlp_kernel<<<MLP_GRID, 128, MLP_SMEM>>>(b1, W2, b2, out);
}

// round 15
// speedup vs baseline: 1.6613x; 1.0408x over previous
#include <cuda_runtime.h>
#include <cuda_fp16.h>
#include <math.h>
#include <stdint.h>

#define NVIEW 5
#define NBINS 128000
#define BATCH 2
#define HF 128
#define WF 128
#define HWF (HF*WF)
#define HI 512
#define WI 512
#define HWI (HI*WI)
#define CF 32
#define HID 256
#define INDIM 73
#define MTOT (BATCH*NBINS)     // 256000
#define NTILES (MTOT/128)      // 2000

#define NK16 5
#define AROWS 44                // smem A row stride (words), bank-conflict-free
#define WROW 44                 // smem B row stride (words)
#define A_S_WORDS (2*128*AROWS) // hi+lo planes
#define B_S_WORDS (HID*WROW)    // hi plane only
#define B_WORDS B_S_WORDS

// ---------------- scratch (device globals: allocation-free, zero-initialized) -------
// +pad entries so unconditional x0+1 / y0+1 corner reads never leave the array.
__device__ float4   g_imgs_t[NVIEW*BATCH*HWI + 600];
__device__ float4   g_feats_t[NVIEW*BATCH*HWF*(CF/4) + 4200];
__device__ uint32_t g_B[B_WORDS];

__device__ __host__ constexpr int word_of(int k) {
    return 8*(k >> 4) + (((k & 15) < 8) ? (k & 15) : ((k & 15) - 7));
}
__device__ __forceinline__ int orig_of(int c) {
    int blk = c >> 4, i = c & 15;
    if (blk == 0) {
        if (i < 3) return i;
        if (i < 6) return 3 + (i - 3);
        if (i < 9) return 38 + (i - 6);
        return -1;
    }
    int cg = blk - 1;
    if (i < 8) return 6 + 8*cg + i;
    return 41 + 8*cg + (i - 8);
}
__device__ __forceinline__ uint32_t pack_h2(float a, float b) {
    __half ha = __float2half_rn(a), hb = __float2half_rn(b);
    return (uint32_t)__half_as_ushort(ha) | ((uint32_t)__half_as_ushort(hb) << 16);
}
__device__ __forceinline__ uint32_t pack_lo2(float a, float b) {
    __half ha = __float2half_rn(a), hb = __float2half_rn(b);
    return pack_h2(a - __half2float(ha), b - __half2float(hb));
}

#define MMA16816(d, a0, a1, a2, a3, b0, b1) \
    asm volatile("mma.sync.aligned.m16n8k16.row.col.f32.f16.f16.f32 " \
        "{%0,%1,%2,%3}, {%4,%5,%6,%7}, {%8,%9}, {%0,%1,%2,%3};" \
        : "+f"((d)[0]), "+f"((d)[1]), "+f"((d)[2]), "+f"((d)[3]) \
        : "r"(a0), "r"(a1), "r"(a2), "r"(a3), "r"(b0), "r"(b1))

// ---------------- prep W1 (hi plane only) ----------------
__global__ void prep_B(const float* __restrict__ W1) {
    int i = blockIdx.x * 256 + threadIdx.x;
    if (i >= HID * 40) return;
    int n = i / 40;
    int k = (i - n * 40) * 2;
    int o0 = orig_of(k), o1 = orig_of(k + 1);
    float v0 = (o0 >= 0) ? W1[o0 * HID + n] : 0.f;
    float v1 = (o1 >= 0) ? W1[o1 * HID + n] : 0.f;
    g_B[n * WROW + word_of(k)] = pack_h2(v0, v1);
}

// ---------------- layout transposes ----------------
__global__ void transpose_imgs(const float* __restrict__ im) {
    int idx = blockIdx.x * blockDim.x + threadIdx.x;
    if (idx >= NVIEW*BATCH*HWI) return;
    int vb = idx >> 18;
    int p  = idx & (HWI - 1);
    const float* base = im + (size_t)vb * 3 * HWI + p;
    g_imgs_t[idx] = make_float4(base[0], base[HWI], base[2*HWI], 0.f);
}
__global__ void transpose_feats(const float* __restrict__ f) {
    __shared__ float tile[32][33];
    int vb = blockIdx.y;
    int p0 = blockIdx.x * 32;
    int tx = threadIdx.x, ty = threadIdx.y;
    tile[ty][tx] = f[((size_t)vb*CF + ty) * HWF + p0 + tx];
    __syncthreads();
    ((float*)g_feats_t)[((size_t)vb*HWF + p0 + ty) * CF + tx] = tile[tx][ty];
}

// ---------------- fused persistent kernel: gather -> smem A -> HMMA -> out ---------
// 256 threads, 2 CTAs/SM. Tile = 128 points.
// smem: As (2 planes x 128 x 44 w) | Bs (256 x 44 w) | bw (256 float2)
#define SMEM_WORDS (A_S_WORDS + B_S_WORDS + 512)
#define SMEM_BYTES (SMEM_WORDS * 4)

__global__ __launch_bounds__(256, 2)
void fused_kernel(const float* __restrict__ grid_, const float* __restrict__ pts,
                  const float* __restrict__ b1, const float* __restrict__ W2,
                  const float* __restrict__ b2, float* __restrict__ out) {
    extern __shared__ uint32_t sm[];
    uint32_t* AsH = sm;                      // [128][44]
    uint32_t* AsL = sm + 128*AROWS;          // [128][44]
    uint32_t* Bs  = sm + A_S_WORDS;          // [256][44]
    float2*  bwS  = (float2*)(sm + A_S_WORDS + B_S_WORDS);

    int tid = threadIdx.x;
    int l = tid & 31, w = tid >> 5;
    int g = l >> 2, t4 = l & 3;
    int q = tid & 7;                         // gather channel-quad

    // ---- one-time: B hi plane + bias/W2 ----
    {
        const uint4* src = (const uint4*)g_B;
        uint4* dst = (uint4*)Bs;
#pragma unroll 4
        for (int i = tid; i < B_S_WORDS/4; i += 256) dst[i] = src[i];
        if (tid < HID) bwS[tid] = make_float2(b1[tid], W2[tid]);
    }
    __syncthreads();

    float b2v = b2[0];

    for (int t = blockIdx.x; t < NTILES; t += gridDim.x) {
        // ================= Phase A: gather 128 pts (4 subtiles of 32) ===============
#pragma unroll 1
        for (int ip = 0; ip < 4; ip++) {
            int lp = (tid >> 3) + 32*ip;     // local point 0..127
            int m = t*128 + lp;
            int b = (m >= NBINS) ? 1 : 0;
            int n = m - b * NBINS;

            float4 s4  = make_float4(0.f,0.f,0.f,0.f), ss4 = make_float4(0.f,0.f,0.f,0.f);
            float3 si  = make_float3(0.f,0.f,0.f),  ssi = make_float3(0.f,0.f,0.f);

#pragma unroll
            for (int v = 0; v < NVIEW; v++) {
                float2 gg = *(const float2*)(grid_ + ((size_t)v*NBINS + n)*2);
                // feats (128x128), 4 channels/lane
                {
                    float fx = fmaf(gg.x, 63.5f, 63.5f);
                    float fy = fmaf(gg.y, 63.5f, 63.5f);
                    int x0 = (int)fx, y0 = (int)fy;
                    float wx1 = fx - (float)x0, wy1 = fy - (float)y0;
                    float wx0 = 1.f - wx1, wy0 = 1.f - wy1;
                    float w00 = wx0*wy0, w01 = wx1*wy0, w10 = wx0*wy1, w11 = wx1*wy1;
                    int pix = (v*BATCH + b) * HWF + y0*WF + x0;
                    const char* p = (const char*)g_feats_t + (size_t)pix*128 + q*16;
                    float4 p00 = *(const float4*)(p);
                    float4 p01 = *(const float4*)(p + 128);
                    float4 p10 = *(const float4*)(p + WF*128);
                    float4 p11 = *(const float4*)(p + WF*128 + 128);
                    float tt;
                    tt = w00*p00.x + w01*p01.x + w10*p10.x + w11*p11.x; s4.x += tt; ss4.x += tt*tt;
                    tt = w00*p00.y + w01*p01.y + w10*p10.y + w11*p11.y; s4.y += tt; ss4.y += tt*tt;
                    tt = w00*p00.z + w01*p01.z + w10*p10.z + w11*p11.z; s4.z += tt; ss4.z += tt*tt;
                    tt = w00*p00.w + w01*p01.w + w10*p10.w + w11*p11.w; s4.w += tt; ss4.w += tt*tt;
                }
                // imgs (512x512): lane q==0 of each point handles all 3 channels
                if (q == 0) {
                    float fx = fmaf(gg.x, 255.5f, 255.5f);
                    float fy = fmaf(gg.y, 255.5f, 255.5f);
                    int x0 = (int)fx, y0 = (int)fy;
                    float wx1 = fx - (float)x0, wy1 = fy - (float)y0;
                    float wx0 = 1.f - wx1, wy0 = 1.f - wy1;
                    float w00 = wx0*wy0, w01 = wx1*wy0, w10 = wx0*wy1, w11 = wx1*wy1;
                    int pix = (v*BATCH + b) * HWI + y0*WI + x0;
                    const char* p = (const char*)g_imgs_t + (size_t)pix*16;
                    float4 p00 = *(const float4*)(p);
                    float4 p01 = *(const float4*)(p + 16);
                    float4 p10 = *(const float4*)(p + WI*16);
                    float4 p11 = *(const float4*)(p + WI*16 + 16);
                    float tt;
                    tt = w00*p00.x + w01*p01.x + w10*p10.x + w11*p11.x; si.x += tt; ssi.x += tt*tt;
                    tt = w00*p00.y + w01*p01.y + w10*p10.y + w11*p11.y; si.y += tt; ssi.y += tt*tt;
                    tt = w00*p00.z + w01*p01.z + w10*p10.z + w11*p11.z; si.z += tt; ssi.z += tt*tt;
                }
            }

            uint32_t* rowH = AsH + lp * AROWS;
            uint32_t* rowL = AsL + lp * AROWS;
            {
                float m0 = s4.x*0.2f, m1 = s4.y*0.2f, m2 = s4.z*0.2f, m3 = s4.w*0.2f;
                float v0 = __expf(-fmaxf(ss4.x*0.2f - m0*m0, 0.f));
                float v1 = __expf(-fmaxf(ss4.y*0.2f - m1*m1, 0.f));
                float v2 = __expf(-fmaxf(ss4.z*0.2f - m2*m2, 0.f));
                float v3 = __expf(-fmaxf(ss4.w*0.2f - m3*m3, 0.f));
                int wslot = 8*(1 + (q >> 1)) + 4*(q & 1);
                *(uint4*)(rowH + wslot) = make_uint4(pack_h2(m0, m1), pack_h2(v0, v1),
                                                     pack_h2(m2, m3), pack_h2(v2, v3));
                *(uint4*)(rowL + wslot) = make_uint4(pack_lo2(m0, m1), pack_lo2(v0, v1),
                                                     pack_lo2(m2, m3), pack_lo2(v2, v3));
            }
            if (q == 0) {
                float im0 = si.x*0.2f, im1 = si.y*0.2f, im2 = si.z*0.2f;
                float iv0 = __expf(-fmaxf(ssi.x*0.2f - im0*im0, 0.f));
                float iv1 = __expf(-fmaxf(ssi.y*0.2f - im1*im1, 0.f));
                float iv2 = __expf(-fmaxf(ssi.z*0.2f - im2*im2, 0.f));
                float p0 = pts[n*3 + 0], p1 = pts[n*3 + 1], p2 = pts[n*3 + 2];
                *(uint4*)(rowH + 0) = make_uint4(pack_h2(p0, p1), pack_h2(iv2, 0.f),
                                                 pack_h2(p2, im0), 0u);
                *(uint4*)(rowH + 4) = make_uint4(pack_h2(im1, im2), 0u,
                                                 pack_h2(iv0, iv1), 0u);
                *(uint4*)(rowL + 0) = make_uint4(pack_lo2(p0, p1), pack_lo2(iv2, 0.f),
                                                 pack_lo2(p2, im0), 0u);
                *(uint4*)(rowL + 4) = make_uint4(pack_lo2(im1, im2), 0u,
                                                 pack_lo2(iv0, iv1), 0u);
            }
        }
        __syncthreads();

        // ================= Phase B: 2-pass HMMA, warp w owns rows w*16..w*16+15 =====
        {
            int m0w = w * 16;
            uint2 aH[NK16][2], aL[NK16][2];
#pragma unroll
            for (int s5 = 0; s5 < NK16; s5++)
#pragma unroll
                for (int rh = 0; rh < 2; rh++) {
                    int off = (m0w + rh*8 + g)*AROWS + s5*8 + 2*t4;
                    aH[s5][rh] = *(const uint2*)(AsH + off);
                    aL[s5][rh] = *(const uint2*)(AsL + off);
                }

            float zp[2] = {0.f, 0.f};

#pragma unroll
            for (int nq = 0; nq < 4; nq++) {
                float acc[8][4];
#pragma unroll
                for (int j = 0; j < 8; j++)
#pragma unroll
                    for (int c = 0; c < 4; c++) acc[j][c] = 0.f;

#pragma unroll
                for (int s5 = 0; s5 < NK16; s5++) {
                    uint2 bh[8];
#pragma unroll
                    for (int j = 0; j < 8; j++) {
                        int ob = (nq*64 + j*8 + g)*WROW + s5*8 + 2*t4;
                        bh[j] = *(const uint2*)(Bs + ob);
                    }
#pragma unroll
                    for (int j = 0; j < 8; j++)
                        MMA16816(acc[j], aH[s5][0].x, aH[s5][1].x,
                                 aH[s5][0].y, aH[s5][1].y, bh[j].x, bh[j].y);
#pragma unroll
                    for (int j = 0; j < 8; j++)
                        MMA16816(acc[j], aL[s5][0].x, aL[s5][1].x,
                                 aL[s5][0].y, aL[s5][1].y, bh[j].x, bh[j].y);
                }
#pragma unroll
                for (int j = 0; j < 8; j++) {
                    int c0 = nq*64 + j*8 + 2*t4;
                    float2 bw0 = bwS[c0];
                    float2 bw1 = bwS[c0 + 1];
                    zp[0] += fmaxf(acc[j][0] + bw0.x, 0.f) * bw0.y
                           + fmaxf(acc[j][1] + bw1.x, 0.f) * bw1.y;
                    zp[1] += fmaxf(acc[j][2] + bw0.x, 0.f) * bw0.y
                           + fmaxf(acc[j][3] + bw1.x, 0.f) * bw1.y;
                }
            }

#pragma unroll
            for (int rh = 0; rh < 2; rh++) {
                float z = zp[rh];
                z += __shfl_xor_sync(0xffffffffu, z, 1);
                z += __shfl_xor_sync(0xffffffffu, z, 2);
                if (t4 == 0) {
                    float zz = z + b2v;
                    // 1 - exp(-softplus(zz)) == sigmoid(zz)
                    out[t*128 + m0w + rh*8 + g] = 1.f / (1.f + expf(-zz));
                }
            }
        }
        __syncthreads();   // protect As before next tile's gather overwrites
    }
}

// ---------------- launch ----------------
extern "C" void kernel_launch(void* const* d_in, const int* in_sizes, int n_in,
                              void* d_out, int out_size) {
    const float* imgs  = (const float*)d_in[0];
    const float* feats = (const float*)d_in[1];
    const float* grid  = (const float*)d_in[2];
    const float* pts   = (const float*)d_in[3];
    const float* W1    = (const float*)d_in[4];
    const float* b1    = (const float*)d_in[5];
    const float* W2    = (const float*)d_in[6];
    const float* b2    = (const float*)d_in[7];
    float* out = (float*)d_out;

    cudaFuncSetAttribute(fused_kernel, cudaFuncAttributeMaxDynamicSharedMemorySize, SMEM_BYTES);

    prep_B<<<(HID*40 + 255)/256, 256>>>(W1);
    transpose_imgs<<<(NVIEW*BATCH*HWI + 255)/256, 256>>>(imgs);
    transpose_feats<<<dim3(HWF/32, NVIEW*BATCH), dim3(32, 32)>>>(feats);
    fused_kernel<<<296, 256, SMEM_BYTES>>>(grid, pts, b1, W2, b2, out);
}

// round 17
// speedup vs baseline: 1.7644x; 1.0621x over previous
#include <cuda_runtime.h>
#include <cuda_fp16.h>
#include <math.h>
#include <stdint.h>

#define NVIEW 5
#define NBINS 128000
#define BATCH 2
#define HF 128
#define WF 128
#define HWF (HF*WF)
#define HI 512
#define WI 512
#define HWI (HI*WI)
#define CF 32
#define HID 256
#define INDIM 73
#define MTOT (BATCH*NBINS)     // 256000

#define TILE 64
#define NTILES (MTOT/TILE)     // 4000
#define NK16 5
#define AROWS 44                // smem A row stride (words)
#define WROW 44                 // smem B row stride (words)
#define A_S_WORDS (2*TILE*AROWS)
#define B_S_WORDS (HID*WROW)
#define B_WORDS B_S_WORDS

// ---------------- scratch (device globals: allocation-free, zero-initialized) -------
__device__ float4   g_imgs_t[NVIEW*BATCH*HWI + 600];
__device__ float4   g_feats_t[NVIEW*BATCH*HWF*(CF/4) + 4200];
__device__ uint32_t g_B[B_WORDS];

__device__ __host__ constexpr int word_of(int k) {
    return 8*(k >> 4) + (((k & 15) < 8) ? (k & 15) : ((k & 15) - 7));
}
__device__ __forceinline__ int orig_of(int c) {
    int blk = c >> 4, i = c & 15;
    if (blk == 0) {
        if (i < 3) return i;
        if (i < 6) return 3 + (i - 3);
        if (i < 9) return 38 + (i - 6);
        return -1;
    }
    int cg = blk - 1;
    if (i < 8) return 6 + 8*cg + i;
    return 41 + 8*cg + (i - 8);
}
__device__ __forceinline__ uint32_t pack_h2(float a, float b) {
    __half ha = __float2half_rn(a), hb = __float2half_rn(b);
    return (uint32_t)__half_as_ushort(ha) | ((uint32_t)__half_as_ushort(hb) << 16);
}
__device__ __forceinline__ uint32_t pack_lo2(float a, float b) {
    __half ha = __float2half_rn(a), hb = __float2half_rn(b);
    return pack_h2(a - __half2float(ha), b - __half2float(hb));
}

#define MMA16816(d, a0, a1, a2, a3, b0, b1) \
    asm volatile("mma.sync.aligned.m16n8k16.row.col.f32.f16.f16.f32 " \
        "{%0,%1,%2,%3}, {%4,%5,%6,%7}, {%8,%9}, {%0,%1,%2,%3};" \
        : "+f"((d)[0]), "+f"((d)[1]), "+f"((d)[2]), "+f"((d)[3]) \
        : "r"(a0), "r"(a1), "r"(a2), "r"(a3), "r"(b0), "r"(b1))

// ---------------- prep W1 (hi plane only) ----------------
__global__ void prep_B(const float* __restrict__ W1) {
    int i = blockIdx.x * 256 + threadIdx.x;
    if (i >= HID * 40) return;
    int n = i / 40;
    int k = (i - n * 40) * 2;
    int o0 = orig_of(k), o1 = orig_of(k + 1);
    float v0 = (o0 >= 0) ? W1[o0 * HID + n] : 0.f;
    float v1 = (o1 >= 0) ? W1[o1 * HID + n] : 0.f;
    g_B[n * WROW + word_of(k)] = pack_h2(v0, v1);
}

// ---------------- layout transposes ----------------
__global__ void transpose_imgs(const float* __restrict__ im) {
    int idx = blockIdx.x * blockDim.x + threadIdx.x;
    if (idx >= NVIEW*BATCH*HWI) return;
    int vb = idx >> 18;
    int p  = idx & (HWI - 1);
    const float* base = im + (size_t)vb * 3 * HWI + p;
    g_imgs_t[idx] = make_float4(base[0], base[HWI], base[2*HWI], 0.f);
}
__global__ void transpose_feats(const float* __restrict__ f) {
    __shared__ float tile[32][33];
    int vb = blockIdx.y;
    int p0 = blockIdx.x * 32;
    int tx = threadIdx.x, ty = threadIdx.y;
    tile[ty][tx] = f[((size_t)vb*CF + ty) * HWF + p0 + tx];
    __syncthreads();
    ((float*)g_feats_t)[((size_t)vb*HWF + p0 + ty) * CF + tx] = tile[tx][ty];
}

// ---------------- fused persistent kernel, 64-pt tiles, 3 CTAs/SM ------------------
// smem: AsH[64][44] AsL[64][44] Bs[256][44] bw[256 f2] zbuf[64][2]
#define SMEM_WORDS (A_S_WORDS + B_S_WORDS + 512 + 128)
#define SMEM_BYTES (SMEM_WORDS * 4)

__global__ __launch_bounds__(256, 3)
void fused_kernel(const float* __restrict__ grid_, const float* __restrict__ pts,
                  const float* __restrict__ b1, const float* __restrict__ W2,
                  const float* __restrict__ b2, float* __restrict__ out) {
    extern __shared__ uint32_t sm[];
    uint32_t* AsH = sm;                          // [64][44]
    uint32_t* AsL = sm + TILE*AROWS;             // [64][44]
    uint32_t* Bs  = sm + A_S_WORDS;              // [256][44]
    float2*  bwS  = (float2*)(sm + A_S_WORDS + B_S_WORDS);
    float*   zbuf = (float*)(bwS + HID);         // [64][2]

    int tid = threadIdx.x;
    int l = tid & 31, w = tid >> 5;
    int g = l >> 2, t4 = l & 3;
    int q = tid & 7;                             // gather channel-quad

    // ---- one-time: B hi plane + bias/W2 ----
    {
        const uint4* src = (const uint4*)g_B;
        uint4* dst = (uint4*)Bs;
#pragma unroll 4
        for (int i = tid; i < B_S_WORDS/4; i += 256) dst[i] = src[i];
        if (tid < HID) bwS[tid] = make_float2(b1[tid], W2[tid]);
    }
    __syncthreads();

    float b2v = b2[0];
    int mw = w & 3, nh = w >> 2;                 // MMA: 4 m-warps x 2 n-halves

    for (int t = blockIdx.x; t < NTILES; t += gridDim.x) {
        // ================= Phase A: gather 64 pts (2 subtiles of 32) ===============
#pragma unroll 1
        for (int ip = 0; ip < 2; ip++) {
            int lp = (tid >> 3) + 32*ip;         // local point 0..63
            int m = t*TILE + lp;
            int b = (m >= NBINS) ? 1 : 0;
            int n = m - b * NBINS;

            float4 s4  = make_float4(0.f,0.f,0.f,0.f), ss4 = make_float4(0.f,0.f,0.f,0.f);
            float3 si  = make_float3(0.f,0.f,0.f),  ssi = make_float3(0.f,0.f,0.f);

#pragma unroll
            for (int v = 0; v < NVIEW; v++) {
                float2 gg = *(const float2*)(grid_ + ((size_t)v*NBINS + n)*2);
                {
                    float fx = fmaf(gg.x, 63.5f, 63.5f);
                    float fy = fmaf(gg.y, 63.5f, 63.5f);
                    int x0 = (int)fx, y0 = (int)fy;
                    float wx1 = fx - (float)x0, wy1 = fy - (float)y0;
                    float wx0 = 1.f - wx1, wy0 = 1.f - wy1;
                    float w00 = wx0*wy0, w01 = wx1*wy0, w10 = wx0*wy1, w11 = wx1*wy1;
                    int pix = (v*BATCH + b) * HWF + y0*WF + x0;
                    const char* p = (const char*)g_feats_t + (size_t)pix*128 + q*16;
                    float4 p00 = *(const float4*)(p);
                    float4 p01 = *(const float4*)(p + 128);
                    float4 p10 = *(const float4*)(p + WF*128);
                    float4 p11 = *(const float4*)(p + WF*128 + 128);
                    float tt;
                    tt = w00*p00.x + w01*p01.x + w10*p10.x + w11*p11.x; s4.x += tt; ss4.x += tt*tt;
                    tt = w00*p00.y + w01*p01.y + w10*p10.y + w11*p11.y; s4.y += tt; ss4.y += tt*tt;
                    tt = w00*p00.z + w01*p01.z + w10*p10.z + w11*p11.z; s4.z += tt; ss4.z += tt*tt;
                    tt = w00*p00.w + w01*p01.w + w10*p10.w + w11*p11.w; s4.w += tt; ss4.w += tt*tt;
                }
                if (q == 0) {
                    float fx = fmaf(gg.x, 255.5f, 255.5f);
                    float fy = fmaf(gg.y, 255.5f, 255.5f);
                    int x0 = (int)fx, y0 = (int)fy;
                    float wx1 = fx - (float)x0, wy1 = fy - (float)y0;
                    float wx0 = 1.f - wx1, wy0 = 1.f - wy1;
                    float w00 = wx0*wy0, w01 = wx1*wy0, w10 = wx0*wy1, w11 = wx1*wy1;
                    int pix = (v*BATCH + b) * HWI + y0*WI + x0;
                    const char* p = (const char*)g_imgs_t + (size_t)pix*16;
                    float4 p00 = *(const float4*)(p);
                    float4 p01 = *(const float4*)(p + 16);
                    float4 p10 = *(const float4*)(p + WI*16);
                    float4 p11 = *(const float4*)(p + WI*16 + 16);
                    float tt;
                    tt = w00*p00.x + w01*p01.x + w10*p10.x + w11*p11.x; si.x += tt; ssi.x += tt*tt;
                    tt = w00*p00.y + w01*p01.y + w10*p10.y + w11*p11.y; si.y += tt; ssi.y += tt*tt;
                    tt = w00*p00.z + w01*p01.z + w10*p10.z + w11*p11.z; si.z += tt; ssi.z += tt*tt;
                }
            }

            uint32_t* rowH = AsH + lp * AROWS;
            uint32_t* rowL = AsL + lp * AROWS;
            {
                float m0 = s4.x*0.2f, m1 = s4.y*0.2f, m2 = s4.z*0.2f, m3 = s4.w*0.2f;
                float v0 = __expf(-fmaxf(ss4.x*0.2f - m0*m0, 0.f));
                float v1 = __expf(-fmaxf(ss4.y*0.2f - m1*m1, 0.f));
                float v2 = __expf(-fmaxf(ss4.z*0.2f - m2*m2, 0.f));
                float v3 = __expf(-fmaxf(ss4.w*0.2f - m3*m3, 0.f));
                int wslot = 8*(1 + (q >> 1)) + 4*(q & 1);
                *(uint4*)(rowH + wslot) = make_uint4(pack_h2(m0, m1), pack_h2(v0, v1),
                                                     pack_h2(m2, m3), pack_h2(v2, v3));
                *(uint4*)(rowL + wslot) = make_uint4(pack_lo2(m0, m1), pack_lo2(v0, v1),
                                                     pack_lo2(m2, m3), pack_lo2(v2, v3));
            }
            if (q == 0) {
                float im0 = si.x*0.2f, im1 = si.y*0.2f, im2 = si.z*0.2f;
                float iv0 = __expf(-fmaxf(ssi.x*0.2f - im0*im0, 0.f));
                float iv1 = __expf(-fmaxf(ssi.y*0.2f - im1*im1, 0.f));
                float iv2 = __expf(-fmaxf(ssi.z*0.2f - im2*im2, 0.f));
                float p0 = pts[n*3 + 0], p1 = pts[n*3 + 1], p2 = pts[n*3 + 2];
                *(uint4*)(rowH + 0) = make_uint4(pack_h2(p0, p1), pack_h2(iv2, 0.f),
                                                 pack_h2(p2, im0), 0u);
                *(uint4*)(rowH + 4) = make_uint4(pack_h2(im1, im2), 0u,
                                                 pack_h2(iv0, iv1), 0u);
                *(uint4*)(rowL + 0) = make_uint4(pack_lo2(p0, p1), pack_lo2(iv2, 0.f),
                                                 pack_lo2(p2, im0), 0u);
                *(uint4*)(rowL + 4) = make_uint4(pack_lo2(im1, im2), 0u,
                                                 pack_lo2(iv0, iv1), 0u);
            }
        }
        __syncthreads();

        // ================= Phase B: warp = (mw, nh); 16 rows x 128 cols =============
        {
            float zp[2] = {0.f, 0.f};
            int arow0 = (mw*16 + g) * AROWS + 2*t4;
            int arow1 = (mw*16 + 8 + g) * AROWS + 2*t4;

#pragma unroll
            for (int nq = 0; nq < 2; nq++) {
                float acc[8][4];
#pragma unroll
                for (int j = 0; j < 8; j++)
#pragma unroll
                    for (int c = 0; c < 4; c++) acc[j][c] = 0.f;

#pragma unroll
                for (int s5 = 0; s5 < NK16; s5++) {
                    uint2 a0 = *(const uint2*)(AsH + arow0 + s5*8);
                    uint2 a1 = *(const uint2*)(AsH + arow1 + s5*8);
                    uint2 c0 = *(const uint2*)(AsL + arow0 + s5*8);
                    uint2 c1 = *(const uint2*)(AsL + arow1 + s5*8);
                    uint2 bh[8];
#pragma unroll
                    for (int j = 0; j < 8; j++) {
                        int ob = (nh*128 + nq*64 + j*8 + g)*WROW + s5*8 + 2*t4;
                        bh[j] = *(const uint2*)(Bs + ob);
                    }
#pragma unroll
                    for (int j = 0; j < 8; j++)
                        MMA16816(acc[j], a0.x, a1.x, a0.y, a1.y, bh[j].x, bh[j].y);
#pragma unroll
                    for (int j = 0; j < 8; j++)
                        MMA16816(acc[j], c0.x, c1.x, c0.y, c1.y, bh[j].x, bh[j].y);
                }
#pragma unroll
                for (int j = 0; j < 8; j++) {
                    int cc = nh*128 + nq*64 + j*8 + 2*t4;
                    float2 bw0 = bwS[cc];
                    float2 bw1 = bwS[cc + 1];
                    zp[0] += fmaxf(acc[j][0] + bw0.x, 0.f) * bw0.y
                           + fmaxf(acc[j][1] + bw1.x, 0.f) * bw1.y;
                    zp[1] += fmaxf(acc[j][2] + bw0.x, 0.f) * bw0.y
                           + fmaxf(acc[j][3] + bw1.x, 0.f) * bw1.y;
                }
            }

#pragma unroll
            for (int rh = 0; rh < 2; rh++) {
                float z = zp[rh];
                z += __shfl_xor_sync(0xffffffffu, z, 1);
                z += __shfl_xor_sync(0xffffffffu, z, 2);
                if (t4 == 0) zbuf[(mw*16 + rh*8 + g)*2 + nh] = z;
            }
        }
        __syncthreads();

        // ================= Phase C: combine n-halves + sigmoid ======================
        if (tid < TILE) {
            float zz = zbuf[tid*2] + zbuf[tid*2 + 1] + b2v;
            // 1 - exp(-softplus(zz)) == sigmoid(zz)
            out[t*TILE + tid] = 1.f / (1.f + expf(-zz));
        }
        // no sync needed: next gather writes As only; zbuf rewritten after next sync.
    }
}

// ---------------- launch ----------------
extern "C" void kernel_launch(void* const* d_in, const int* in_sizes, int n_in,
                              void* d_out, int out_size) {
    const float* imgs  = (const float*)d_in[0];
    const float* feats = (const float*)d_in[1];
    const float* grid  = (const float*)d_in[2];
    const float* pts   = (const float*)d_in[3];
    const float* W1    = (const float*)d_in[4];
    const float* b1    = (const float*)d_in[5];
    const float* W2    = (const float*)d_in[6];
    const float* b2    = (const float*)d_in[7];
    float* out = (float*)d_out;

    cudaFuncSetAttribute(fused_kernel, cudaFuncAttributeMaxDynamicSharedMemorySize, SMEM_BYTES);

    prep_B<<<(HID*40 + 255)/256, 256>>>(W1);
    transpose_imgs<<<(NVIEW*BATCH*HWI + 255)/256, 256>>>(imgs);
    transpose_feats<<<dim3(HWF/32, NVIEW*BATCH), dim3(32, 32)>>>(feats);
    fused_kernel<<<444, 256, SMEM_BYTES>>>(grid, pts, b1, W2, b2, out);
}